// round 2
// baseline (speedup 1.0000x reference)
#include <cuda_runtime.h>
#include <math.h>

#define TT 512
#define BB 128
#define DIN 512
#define HD 512
#define NR 2048              // 4 gates * HD
#define MTOT (TT * BB)       // 65536

// ---------------- scratch (no allocations allowed) ----------------
__device__ float g_Wx[NR * DIN];                 // [r][k]  x-part of weights
__device__ float g_Wh[NR * HD];                  // [r][k]  h-part of weights
__device__ float g_bias[NR];
__device__ float g_xproj[(size_t)NR * MTOT];     // [r][m], m = t*128+b  (512MB)
__device__ float g_hT[2][HD * BB];               // transposed h: [j][b], double buffered
__device__ float g_cT[HD * BB];                  // transposed c: [j][b]

// ---------------- pack weights + zero state ----------------
__global__ void pack_kernel(const float* __restrict__ Wf, const float* __restrict__ Wi,
                            const float* __restrict__ Wg_, const float* __restrict__ Wo,
                            const float* __restrict__ bf, const float* __restrict__ bi,
                            const float* __restrict__ bg, const float* __restrict__ bo) {
    int idx = blockIdx.x * blockDim.x + threadIdx.x;
    if (idx < NR * DIN) {
        int r = idx >> 9;          // gate-row 0..2047
        int k = idx & 511;
        int gate = r >> 9;         // 0=f 1=i 2=g 3=o
        int j = r & 511;
        const float* W = (gate == 0) ? Wf : (gate == 1) ? Wi : (gate == 2) ? Wg_ : Wo;
        g_Wx[idx] = W[j * 1024 + k];
        g_Wh[idx] = W[j * 1024 + 512 + k];
        if (k == 0) {
            const float* bb = (gate == 0) ? bf : (gate == 1) ? bi : (gate == 2) ? bg : bo;
            g_bias[r] = bb[j];
        }
    }
    if (idx < HD * BB) {
        g_hT[0][idx] = 0.f;
        g_cT[idx] = 0.f;
    }
}

// ---------------- xproj GEMM: C[r][m] = bias[r] + sum_k Wx[r][k]*X[m][k] ----------------
// blockIdx.x -> m tile (512 tiles of 128), blockIdx.y -> r tile (16 tiles of 128)
__global__ void __launch_bounds__(256) xproj_gemm(const float* __restrict__ X) {
    __shared__ float Ws[16][132];   // [k][r] padded
    __shared__ float Xs[16][132];   // [k][m] padded
    int tid = threadIdx.x;
    int r0 = blockIdx.y * 128;
    int m0 = blockIdx.x * 128;
    int ty = tid >> 4;   // 0..15 -> r micro block of 8
    int tx = tid & 15;   // 0..15 -> m micro block of 8

    float acc[8][8];
#pragma unroll
    for (int i = 0; i < 8; i++)
#pragma unroll
        for (int j = 0; j < 8; j++) acc[i][j] = 0.f;

    for (int kt = 0; kt < DIN; kt += 16) {
#pragma unroll
        for (int q = 0; q < 2; q++) {
            int f = tid + q * 256;         // 0..511  (128 rows x 4 float4)
            int row = f >> 2;
            int kq = (f & 3) * 4;
            float4 a = *(const float4*)&g_Wx[(size_t)(r0 + row) * DIN + kt + kq];
            float4 b = *(const float4*)&X[(size_t)(m0 + row) * DIN + kt + kq];
            Ws[kq + 0][row] = a.x; Ws[kq + 1][row] = a.y; Ws[kq + 2][row] = a.z; Ws[kq + 3][row] = a.w;
            Xs[kq + 0][row] = b.x; Xs[kq + 1][row] = b.y; Xs[kq + 2][row] = b.z; Xs[kq + 3][row] = b.w;
        }
        __syncthreads();
#pragma unroll
        for (int kk = 0; kk < 16; kk++) {
            float a[8], b[8];
            *(float4*)&a[0] = *(float4*)&Ws[kk][ty * 8];
            *(float4*)&a[4] = *(float4*)&Ws[kk][ty * 8 + 4];
            *(float4*)&b[0] = *(float4*)&Xs[kk][tx * 8];
            *(float4*)&b[4] = *(float4*)&Xs[kk][tx * 8 + 4];
#pragma unroll
            for (int i = 0; i < 8; i++)
#pragma unroll
                for (int j = 0; j < 8; j++) acc[i][j] += a[i] * b[j];
        }
        __syncthreads();
    }
#pragma unroll
    for (int i = 0; i < 8; i++) {
        int r = r0 + ty * 8 + i;
        float bias = g_bias[r];
        float* Crow = &g_xproj[(size_t)r * MTOT + m0 + tx * 8];
        float4 v0 = make_float4(acc[i][0] + bias, acc[i][1] + bias, acc[i][2] + bias, acc[i][3] + bias);
        float4 v1 = make_float4(acc[i][4] + bias, acc[i][5] + bias, acc[i][6] + bias, acc[i][7] + bias);
        *(float4*)&Crow[0] = v0;
        *(float4*)&Crow[4] = v1;
    }
}

__device__ __forceinline__ float sigf(float x) { return 1.f / (1.f + expf(-x)); }

// ---------------- one LSTM timestep ----------------
// grid 128 CTAs x 128 threads. CTA owns hidden units j0..j0+3 (x 4 gates = 16 W rows).
__global__ void __launch_bounds__(128) lstm_step(float* __restrict__ out, int t) {
    __shared__ float sW[16][512];    // 16 weight rows (h-part), 32KB
    __shared__ float sbuf[16][132];  // h chunk during mainloop, then gate pre-acts
    int tid = threadIdx.x;
    int lane = tid & 31;
    int rg = tid >> 5;               // warp id == gate id 0..3
    int j0 = blockIdx.x * 4;
    int p = t & 1;
    const float* __restrict__ hprev = g_hT[p];

    // load 16 weight rows: lr -> global r = (lr/4)*512 + j0 + (lr%4)
#pragma unroll
    for (int lr = 0; lr < 16; lr++) {
        int r = (lr >> 2) * 512 + j0 + (lr & 3);
        *(float4*)&sW[lr][tid * 4] = *(const float4*)&g_Wh[(size_t)r * 512 + tid * 4];
    }

    float acc[4][4];
#pragma unroll
    for (int i = 0; i < 4; i++)
#pragma unroll
        for (int q = 0; q < 4; q++) acc[i][q] = 0.f;

    for (int kc = 0; kc < 32; kc++) {
        __syncthreads();  // previous chunk (or weight-load) consumers done
#pragma unroll
        for (int q = 0; q < 4; q++) {
            int f = tid + q * 128;     // 0..511 float4s: 16 k-rows x 32 float4
            int rr = f >> 5;
            int c4 = (f & 31) * 4;
            *(float4*)&sbuf[rr][c4] = *(const float4*)&hprev[(kc * 16 + rr) * 128 + c4];
        }
        __syncthreads();
#pragma unroll
        for (int kk = 0; kk < 16; kk++) {
            float w0 = sW[rg * 4 + 0][kc * 16 + kk];
            float w1 = sW[rg * 4 + 1][kc * 16 + kk];
            float w2 = sW[rg * 4 + 2][kc * 16 + kk];
            float w3 = sW[rg * 4 + 3][kc * 16 + kk];
            float h0 = sbuf[kk][lane];
            float h1 = sbuf[kk][lane + 32];
            float h2 = sbuf[kk][lane + 64];
            float h3 = sbuf[kk][lane + 96];
            acc[0][0] += w0 * h0; acc[0][1] += w0 * h1; acc[0][2] += w0 * h2; acc[0][3] += w0 * h3;
            acc[1][0] += w1 * h0; acc[1][1] += w1 * h1; acc[1][2] += w1 * h2; acc[1][3] += w1 * h3;
            acc[2][0] += w2 * h0; acc[2][1] += w2 * h1; acc[2][2] += w2 * h2; acc[2][3] += w2 * h3;
            acc[3][0] += w3 * h0; acc[3][1] += w3 * h1; acc[3][2] += w3 * h2; acc[3][3] += w3 * h3;
        }
    }
    __syncthreads();

    // add xproj (bias already folded) and stash pre-activations in sbuf as [lr][b]
#pragma unroll
    for (int i = 0; i < 4; i++) {
        int r = rg * 512 + j0 + i;
        const float* __restrict__ xr = &g_xproj[(size_t)r * MTOT + (size_t)t * 128];
#pragma unroll
        for (int q = 0; q < 4; q++) {
            int b = lane + 32 * q;
            sbuf[rg * 4 + i][b] = acc[i][q] + xr[b];
        }
    }
    __syncthreads();

    // combine gates: cell = q*128+tid -> u = cell&3, b = cell>>2
    float* __restrict__ hnext = g_hT[p ^ 1];
#pragma unroll
    for (int q = 0; q < 4; q++) {
        int cell = q * 128 + tid;      // 0..511
        int u = cell & 3;
        int b = cell >> 2;
        float pf = sbuf[0 + u][b];
        float pi = sbuf[4 + u][b];
        float pg = sbuf[8 + u][b];
        float po = sbuf[12 + u][b];
        float fg = sigf(pf);
        float ig = sigf(pi);
        float gg = tanhf(pg);
        float og = sigf(po);
        int j = j0 + u;
        float cold = g_cT[j * 128 + b];
        float cn = fg * cold + ig * gg;
        float hn = og * tanhf(cn);
        g_cT[j * 128 + b] = cn;
        hnext[j * 128 + b] = hn;
        out[((size_t)t * 128 + b) * 512 + j] = hn;
    }
}

// ---------------- emit hx, cx tail ----------------
__global__ void finalize_kernel(float* __restrict__ out) {
    int idx = blockIdx.x * blockDim.x + threadIdx.x;  // idx = b*512 + j
    if (idx < HD * BB) {
        int b = idx >> 9;
        int j = idx & 511;
        size_t base = (size_t)TT * BB * HD;
        out[base + idx] = g_hT[0][j * 128 + b];            // 512 steps -> final h in buffer 0
        out[base + (size_t)BB * HD + idx] = g_cT[j * 128 + b];
    }
}

extern "C" void kernel_launch(void* const* d_in, const int* in_sizes, int n_in,
                              void* d_out, int out_size) {
    const float* X  = (const float*)d_in[0];
    const float* Wf = (const float*)d_in[1];
    const float* bf = (const float*)d_in[2];
    const float* Wi = (const float*)d_in[3];
    const float* bi = (const float*)d_in[4];
    const float* Wg = (const float*)d_in[5];
    const float* bg = (const float*)d_in[6];
    const float* Wo = (const float*)d_in[7];
    const float* bo = (const float*)d_in[8];
    float* out = (float*)d_out;

    pack_kernel<<<(NR * DIN + 255) / 256, 256>>>(Wf, Wi, Wg, Wo, bf, bi, bg, bo);
    dim3 ggrid(MTOT / 128, NR / 128);   // (512, 16)
    xproj_gemm<<<ggrid, 256>>>(X);
    for (int t = 0; t < TT; t++)
        lstm_step<<<128, 128>>>(out, t);
    finalize_kernel<<<(HD * BB + 255) / 256, 256>>>(out);
}

// round 8
// speedup vs baseline: 1.3518x; 1.3518x over previous
#include <cuda_runtime.h>
#include <cuda_bf16.h>
#include <math.h>
#include <stdint.h>

#define TT 512
#define BB 128
#define DIN 512
#define HD 512
#define NR 2048
#define MTOT (TT * BB)          // 65536
#define OUTBASE ((size_t)TT * BB * HD)

// ---------------- scratch ----------------
__device__ __nv_bfloat16 g_Xhi[(size_t)MTOT * DIN];
__device__ __nv_bfloat16 g_Xlo[(size_t)MTOT * DIN];
__device__ __nv_bfloat16 g_Whi[NR * DIN];
__device__ __nv_bfloat16 g_Wlo[NR * DIN];
__device__ float g_Wh[NR * HD];
__device__ float g_bias[NR];
__device__ float g_xproj[(size_t)NR * MTOT];     // [r][m]
__device__ float g_hT[2][HD * BB];               // [j][b] double buffered
__device__ int g_bar;
__device__ unsigned g_gen;

// ---------------- PTX helpers (sm_80-compatible ISA only) ----------------
__device__ __forceinline__ uint32_t smem_u32(const void* p) {
    uint32_t a;
    asm("{ .reg .u64 t; cvta.to.shared.u64 t, %1; cvt.u32.u64 %0, t; }" : "=r"(a) : "l"(p));
    return a;
}

__device__ __forceinline__ void ldsm4(uint32_t& r0, uint32_t& r1, uint32_t& r2, uint32_t& r3,
                                      uint32_t addr) {
    asm volatile("ldmatrix.sync.aligned.m8n8.x4.shared.b16 {%0,%1,%2,%3}, [%4];"
                 : "=r"(r0), "=r"(r1), "=r"(r2), "=r"(r3) : "r"(addr));
}

__device__ __forceinline__ void mma16816(float* c, const uint32_t* a, const uint32_t* b) {
    asm volatile("mma.sync.aligned.m16n8k16.row.col.f32.bf16.bf16.f32 "
                 "{%0,%1,%2,%3}, {%4,%5,%6,%7}, {%8,%9}, {%0,%1,%2,%3};"
                 : "+f"(c[0]), "+f"(c[1]), "+f"(c[2]), "+f"(c[3])
                 : "r"(a[0]), "r"(a[1]), "r"(a[2]), "r"(a[3]), "r"(b[0]), "r"(b[1]));
}

// ---------------- pack weights, split into bf16 hi/lo, zero h0 ----------------
__global__ void pack_kernel(const float* __restrict__ Wf, const float* __restrict__ Wi,
                            const float* __restrict__ Wg_, const float* __restrict__ Wo,
                            const float* __restrict__ bf, const float* __restrict__ bi,
                            const float* __restrict__ bg, const float* __restrict__ bo) {
    int idx = blockIdx.x * blockDim.x + threadIdx.x;
    if (idx < NR * DIN) {
        int r = idx >> 9;
        int k = idx & 511;
        int gate = r >> 9;
        int j = r & 511;
        const float* W = (gate == 0) ? Wf : (gate == 1) ? Wi : (gate == 2) ? Wg_ : Wo;
        float wx = W[j * 1024 + k];
        __nv_bfloat16 hi = __float2bfloat16(wx);
        g_Whi[idx] = hi;
        g_Wlo[idx] = __float2bfloat16(wx - __bfloat162float(hi));
        g_Wh[idx] = W[j * 1024 + 512 + k];
        if (k == 0) {
            const float* bb = (gate == 0) ? bf : (gate == 1) ? bi : (gate == 2) ? bg : bo;
            g_bias[r] = bb[j];
        }
    }
    if (idx < HD * BB) g_hT[0][idx] = 0.f;
}

// ---------------- split X into bf16 hi/lo ----------------
__global__ void split_x(const float* __restrict__ X) {
    size_t i = (size_t)blockIdx.x * blockDim.x + threadIdx.x;  // float4 index
    if (i < (size_t)MTOT * DIN / 4) {
        float4 v = __ldg((const float4*)X + i);
        __nv_bfloat16 h0 = __float2bfloat16(v.x), h1 = __float2bfloat16(v.y);
        __nv_bfloat16 h2 = __float2bfloat16(v.z), h3 = __float2bfloat16(v.w);
        __nv_bfloat162* ph = (__nv_bfloat162*)g_Xhi;
        __nv_bfloat162* pl = (__nv_bfloat162*)g_Xlo;
        ph[i * 2] = __nv_bfloat162(h0, h1);
        ph[i * 2 + 1] = __nv_bfloat162(h2, h3);
        pl[i * 2] = __nv_bfloat162(__float2bfloat16(v.x - __bfloat162float(h0)),
                                   __float2bfloat16(v.y - __bfloat162float(h1)));
        pl[i * 2 + 1] = __nv_bfloat162(__float2bfloat16(v.z - __bfloat162float(h2)),
                                       __float2bfloat16(v.w - __bfloat162float(h3)));
    }
}

// ---------------- xproj via mma.sync: C[r][m] = bias[r] + sum_k Wx[r][k] X[m][k] ----------------
// grid (512 m-tiles, 16 r-tiles) x 256 threads. Warps 2(r) x 4(m), warp tile 64x32.
// K chunked by 64 bf16. SMEM: 4 matrices (Ahi, Alo, Bhi, Blo), each 128 rows x 64 bf16
// stored as 8x8-b16 tiles: tile (rt, kt8) at byte (rt*8 + kt8)*128, row-in-tile*16.
__global__ void __launch_bounds__(256) xproj_mma(int dummy) {
    extern __shared__ char smraw[];
    char* smp = (char*)(((uintptr_t)smraw + 127) & ~(uintptr_t)127);
    uint32_t ub = smem_u32(smp);
    int tid = threadIdx.x, wid = tid >> 5, lane = tid & 31;
    int wr = wid & 1, wm = wid >> 1;
    int r0 = blockIdx.y * 128, m0 = blockIdx.x * 128;

    float acc[4][4][4];
#pragma unroll
    for (int f = 0; f < 4; f++)
#pragma unroll
        for (int mf = 0; mf < 4; mf++)
#pragma unroll
            for (int q = 0; q < 4; q++) acc[f][mf][q] = 0.f;

    const __nv_bfloat16* srcs[4] = {
        g_Whi + (size_t)r0 * DIN, g_Wlo + (size_t)r0 * DIN,
        g_Xhi + (size_t)m0 * DIN, g_Xlo + (size_t)m0 * DIN };

    for (int kc = 0; kc < 8; kc++) {
        __syncthreads();
#pragma unroll
        for (int mat = 0; mat < 4; mat++) {
            const float4* src = (const float4*)srcs[mat];
            char* dst = smp + mat * 16384;
#pragma unroll
            for (int it = 0; it < 4; it++) {
                int idx = tid + it * 256;          // 0..1023
                int row = idx & 127;
                int kt8 = idx >> 7;                // 0..7 (exact: tid>>7 + it*2)
                uint32_t off = (uint32_t)(((row >> 3) * 8 + kt8) * 128 + (row & 7) * 16);
                *(float4*)(dst + off) = __ldg(src + (size_t)row * 64 + kc * 8 + kt8);
            }
        }
        __syncthreads();
        uint32_t aH = ub, aL = ub + 16384, bH = ub + 32768, bL = ub + 49152;
#pragma unroll
        for (int kk = 0; kk < 4; kk++) {
            uint32_t aoff[4], boff[2];
#pragma unroll
            for (int f = 0; f < 4; f++)
                aoff[f] = (uint32_t)(((wr * 8 + f * 2 + ((lane >> 3) & 1)) * 8
                                      + (2 * kk + (lane >> 4))) * 128 + (lane & 7) * 16);
#pragma unroll
            for (int p = 0; p < 2; p++)
                boff[p] = (uint32_t)(((wm * 4 + 2 * p + (lane >> 4)) * 8
                                      + (2 * kk + ((lane >> 3) & 1))) * 128 + (lane & 7) * 16);

            uint32_t ah[4][4], bh[4][2];
#pragma unroll
            for (int f = 0; f < 4; f++)
                ldsm4(ah[f][0], ah[f][1], ah[f][2], ah[f][3], aH + aoff[f]);
#pragma unroll
            for (int p = 0; p < 2; p++)
                ldsm4(bh[2 * p][0], bh[2 * p][1], bh[2 * p + 1][0], bh[2 * p + 1][1],
                      bH + boff[p]);
#pragma unroll
            for (int f = 0; f < 4; f++)
#pragma unroll
                for (int mf = 0; mf < 4; mf++)
                    mma16816(acc[f][mf], ah[f], bh[mf]);
            {   // A_hi x B_lo
                uint32_t bl[4][2];
#pragma unroll
                for (int p = 0; p < 2; p++)
                    ldsm4(bl[2 * p][0], bl[2 * p][1], bl[2 * p + 1][0], bl[2 * p + 1][1],
                          bL + boff[p]);
#pragma unroll
                for (int f = 0; f < 4; f++)
#pragma unroll
                    for (int mf = 0; mf < 4; mf++)
                        mma16816(acc[f][mf], ah[f], bl[mf]);
            }
            {   // A_lo x B_hi
#pragma unroll
                for (int f = 0; f < 4; f++) {
                    uint32_t av[4];
                    ldsm4(av[0], av[1], av[2], av[3], aL + aoff[f]);
#pragma unroll
                    for (int mf = 0; mf < 4; mf++)
                        mma16816(acc[f][mf], av, bh[mf]);
                }
            }
        }
    }
    // epilogue: c0=(g,2t) c1=(g,2t+1) c2=(g+8,2t) c3=(g+8,2t+1)
    int g = lane >> 2, t2 = (lane & 3) * 2;
#pragma unroll
    for (int f = 0; f < 4; f++) {
        int r = r0 + wr * 64 + f * 16 + g;
        float b0 = __ldg(&g_bias[r]);
        float b1 = __ldg(&g_bias[r + 8]);
#pragma unroll
        for (int mf = 0; mf < 4; mf++) {
            int m = m0 + wm * 32 + mf * 8 + t2;
            float2 v0 = make_float2(acc[f][mf][0] + b0, acc[f][mf][1] + b0);
            float2 v1 = make_float2(acc[f][mf][2] + b1, acc[f][mf][3] + b1);
            *(float2*)&g_xproj[(size_t)r * MTOT + m] = v0;
            *(float2*)&g_xproj[(size_t)(r + 8) * MTOT + m] = v1;
        }
    }
}

// ---------------- persistent LSTM recurrence ----------------
__device__ __forceinline__ float sigf(float x) { return 1.f / (1.f + expf(-x)); }

__device__ __forceinline__ void grid_sync(int nblocks) {
    __threadfence();
    __syncthreads();
    if (threadIdx.x == 0) {
        unsigned old = *(volatile unsigned*)&g_gen;
        int my = atomicAdd(&g_bar, 1);
        if (my == nblocks - 1) {
            g_bar = 0;
            __threadfence();
            atomicAdd(&g_gen, 1);
        } else {
            while (*(volatile unsigned*)&g_gen == old) {}
        }
        __threadfence();
    }
    __syncthreads();
}

// grid 128 CTAs x 256 threads. CTA owns hidden units j0..j0+3 (16 gate rows).
// warps 0-3: gates f/i/g/o over k[0,256); warps 4-7: same gates over k[256,512).
__global__ void __launch_bounds__(256, 1) lstm_persist(float* __restrict__ out) {
    extern __shared__ char smraw[];
    float* sW = (float*)smraw;                 // [16][512]
    float* hb = sW + 16 * 512;                 // [32][132]
    float* sr = hb + 32 * 132;                 // [16][132]
    int tid = threadIdx.x;
    int wid = tid >> 5, lane = tid & 31;
    int half = wid >> 2, rg = wid & 3;
    int j0 = blockIdx.x * 4;

    // load 16 weight rows once (fp32, 32KB)
    for (int i = tid; i < 2048; i += 256) {    // float4 count
        int lr = i >> 7;
        int c4 = (i & 127) * 4;
        int r = (lr >> 2) * 512 + j0 + (lr & 3);
        *(float4*)&sW[lr * 512 + c4] = *(const float4*)&g_Wh[(size_t)r * 512 + c4];
    }

    float creg[2] = {0.f, 0.f};
    int cu = tid & 3;
    int cb = tid >> 2;

    for (int t = 0; t < TT; t++) {
        const float* __restrict__ hp = g_hT[t & 1];
        float* __restrict__ hn = g_hT[(t & 1) ^ 1];

        float4 xp[4];
        if (half == 0) {
#pragma unroll
            for (int i = 0; i < 4; i++)
                xp[i] = __ldg((const float4*)&g_xproj[(size_t)(rg * 512 + j0 + i) * MTOT
                                                      + (size_t)t * 128 + lane * 4]);
        }

        float acc[4][4];
#pragma unroll
        for (int i = 0; i < 4; i++)
#pragma unroll
            for (int q = 0; q < 4; q++) acc[i][q] = 0.f;

        float4 pre[4];
#pragma unroll
        for (int q = 0; q < 4; q++) {
            int f = tid + q * 256;
            int rr = f >> 5, c4 = (f & 31) * 4;
            int kg = (rr < 16) ? rr : 256 + (rr - 16);
            pre[q] = __ldcg((const float4*)&hp[kg * 128 + c4]);
        }

        for (int kc = 0; kc < 16; kc++) {
            __syncthreads();
#pragma unroll
            for (int q = 0; q < 4; q++) {
                int f = tid + q * 256;
                int rr = f >> 5, c4 = (f & 31) * 4;
                *(float4*)&hb[rr * 132 + c4] = pre[q];
            }
            __syncthreads();
            if (kc < 15) {
#pragma unroll
                for (int q = 0; q < 4; q++) {
                    int f = tid + q * 256;
                    int rr = f >> 5, c4 = (f & 31) * 4;
                    int kg = (rr < 16) ? (kc + 1) * 16 + rr : 256 + (kc + 1) * 16 + (rr - 16);
                    pre[q] = __ldcg((const float4*)&hp[kg * 128 + c4]);
                }
            }
            int kb0 = half * 256 + kc * 16;
            int hr0 = half * 16;
#pragma unroll
            for (int kq = 0; kq < 4; kq++) {
                float4 w0 = *(const float4*)&sW[(rg * 4 + 0) * 512 + kb0 + kq * 4];
                float4 w1 = *(const float4*)&sW[(rg * 4 + 1) * 512 + kb0 + kq * 4];
                float4 w2 = *(const float4*)&sW[(rg * 4 + 2) * 512 + kb0 + kq * 4];
                float4 w3 = *(const float4*)&sW[(rg * 4 + 3) * 512 + kb0 + kq * 4];
                const float* w0p = (const float*)&w0;
                const float* w1p = (const float*)&w1;
                const float* w2p = (const float*)&w2;
                const float* w3p = (const float*)&w3;
#pragma unroll
                for (int s = 0; s < 4; s++) {
                    float4 hv = *(const float4*)&hb[(hr0 + kq * 4 + s) * 132 + lane * 4];
                    const float* hvp = (const float*)&hv;
                    float a0 = w0p[s], a1 = w1p[s], a2 = w2p[s], a3 = w3p[s];
#pragma unroll
                    for (int q = 0; q < 4; q++) {
                        float h = hvp[q];
                        acc[0][q] += a0 * h;
                        acc[1][q] += a1 * h;
                        acc[2][q] += a2 * h;
                        acc[3][q] += a3 * h;
                    }
                }
            }
        }

        if (half == 1) {
#pragma unroll
            for (int i = 0; i < 4; i++)
                *(float4*)&sr[(rg * 4 + i) * 132 + lane * 4] =
                    make_float4(acc[i][0], acc[i][1], acc[i][2], acc[i][3]);
        }
        __syncthreads();
        if (half == 0) {
#pragma unroll
            for (int i = 0; i < 4; i++) {
                float4 o = *(const float4*)&sr[(rg * 4 + i) * 132 + lane * 4];
                const float* xpp = (const float*)&xp[i];
                o.x += acc[i][0] + xpp[0];
                o.y += acc[i][1] + xpp[1];
                o.z += acc[i][2] + xpp[2];
                o.w += acc[i][3] + xpp[3];
                *(float4*)&sr[(rg * 4 + i) * 132 + lane * 4] = o;
            }
        }
        __syncthreads();

#pragma unroll
        for (int e = 0; e < 2; e++) {
            int b = cb + e * 64;
            float pf = sr[(0 + cu) * 132 + b];
            float pi = sr[(4 + cu) * 132 + b];
            float pg = sr[(8 + cu) * 132 + b];
            float po = sr[(12 + cu) * 132 + b];
            float fg = sigf(pf);
            float ig = sigf(pi);
            float gg = tanhf(pg);
            float og = sigf(po);
            float cn = fg * creg[e] + ig * gg;
            creg[e] = cn;
            float hv = og * tanhf(cn);
            hn[(j0 + cu) * 128 + b] = hv;
            out[((size_t)t * 128 + b) * 512 + j0 + cu] = hv;
            if (t == TT - 1) {
                out[OUTBASE + (size_t)b * 512 + j0 + cu] = hv;
                out[OUTBASE + (size_t)BB * HD + (size_t)b * 512 + j0 + cu] = cn;
            }
        }
        grid_sync(128);
    }
}

extern "C" void kernel_launch(void* const* d_in, const int* in_sizes, int n_in,
                              void* d_out, int out_size) {
    const float* X  = (const float*)d_in[0];
    const float* Wf = (const float*)d_in[1];
    const float* bf = (const float*)d_in[2];
    const float* Wi = (const float*)d_in[3];
    const float* bi = (const float*)d_in[4];
    const float* Wg = (const float*)d_in[5];
    const float* bg = (const float*)d_in[6];
    const float* Wo = (const float*)d_in[7];
    const float* bo = (const float*)d_in[8];
    float* out = (float*)d_out;

    const int mma_smem = 4 * 16384 + 128;                      // ~64.1KB
    const int per_smem = (16 * 512 + 32 * 132 + 16 * 132) * 4; // ~58KB
    cudaFuncSetAttribute(xproj_mma, cudaFuncAttributeMaxDynamicSharedMemorySize, mma_smem);
    cudaFuncSetAttribute(lstm_persist, cudaFuncAttributeMaxDynamicSharedMemorySize, per_smem);

    pack_kernel<<<(NR * DIN + 255) / 256, 256>>>(Wf, Wi, Wg, Wo, bf, bi, bg, bo);
    split_x<<<(int)(((size_t)MTOT * DIN / 4 + 255) / 256), 256>>>(X);
    dim3 ggrid(MTOT / 128, NR / 128);   // (512, 16)
    xproj_mma<<<ggrid, 256, mma_smem>>>(0);
    lstm_persist<<<128, 256, per_smem>>>(out);
}

// round 9
// speedup vs baseline: 1.4961x; 1.1067x over previous
#include <cuda_runtime.h>
#include <cuda_bf16.h>
#include <math.h>
#include <stdint.h>

#define TT 512
#define BB 128
#define DIN 512
#define HD 512
#define NR 2048
#define MTOT (TT * BB)          // 65536
#define OUTBASE ((size_t)TT * BB * HD)

// ---------------- scratch ----------------
__device__ __nv_bfloat16 g_Xhi[(size_t)MTOT * DIN];
__device__ __nv_bfloat16 g_Xlo[(size_t)MTOT * DIN];
__device__ __nv_bfloat16 g_Whi[NR * DIN];        // x-part weights hi
__device__ __nv_bfloat16 g_Wlo[NR * DIN];        // x-part weights lo
__device__ __nv_bfloat16 g_Rhi[NR * HD];         // h-part weights hi
__device__ __nv_bfloat16 g_Rlo[NR * HD];         // h-part weights lo
__device__ float g_bias[NR];
__device__ float g_xproj[(size_t)NR * MTOT];     // [r][m]
__device__ __nv_bfloat16 g_hbhi[2][BB * HD];     // h hi, [b][k], double buffered
__device__ __nv_bfloat16 g_hblo[2][BB * HD];     // h lo
__device__ int g_bar;
__device__ unsigned g_gen;

// ---------------- PTX helpers (sm_80-compatible ISA only) ----------------
__device__ __forceinline__ uint32_t smem_u32(const void* p) {
    uint32_t a;
    asm("{ .reg .u64 t; cvta.to.shared.u64 t, %1; cvt.u32.u64 %0, t; }" : "=r"(a) : "l"(p));
    return a;
}

__device__ __forceinline__ void ldsm4(uint32_t& r0, uint32_t& r1, uint32_t& r2, uint32_t& r3,
                                      uint32_t addr) {
    asm volatile("ldmatrix.sync.aligned.m8n8.x4.shared.b16 {%0,%1,%2,%3}, [%4];"
                 : "=r"(r0), "=r"(r1), "=r"(r2), "=r"(r3) : "r"(addr));
}

__device__ __forceinline__ void mma16816(float* c, const uint32_t* a, const uint32_t* b) {
    asm volatile("mma.sync.aligned.m16n8k16.row.col.f32.bf16.bf16.f32 "
                 "{%0,%1,%2,%3}, {%4,%5,%6,%7}, {%8,%9}, {%0,%1,%2,%3};"
                 : "+f"(c[0]), "+f"(c[1]), "+f"(c[2]), "+f"(c[3])
                 : "r"(a[0]), "r"(a[1]), "r"(a[2]), "r"(a[3]), "r"(b[0]), "r"(b[1]));
}

__device__ __forceinline__ void cpasync16(uint32_t saddr, const void* g) {
    asm volatile("cp.async.cg.shared.global [%0], [%1], 16;" :: "r"(saddr), "l"(g));
}
#define CP_COMMIT() asm volatile("cp.async.commit_group;" ::: "memory")
#define CP_WAIT1()  asm volatile("cp.async.wait_group 1;" ::: "memory")
#define CP_WAIT0()  asm volatile("cp.async.wait_group 0;" ::: "memory")

// ---------------- pack weights (bf16 hi/lo both halves), zero h0 ----------------
__global__ void pack_kernel(const float* __restrict__ Wf, const float* __restrict__ Wi,
                            const float* __restrict__ Wg_, const float* __restrict__ Wo,
                            const float* __restrict__ bf, const float* __restrict__ bi,
                            const float* __restrict__ bg, const float* __restrict__ bo) {
    int idx = blockIdx.x * blockDim.x + threadIdx.x;
    if (idx < NR * DIN) {
        int r = idx >> 9;
        int k = idx & 511;
        int gate = r >> 9;
        int j = r & 511;
        const float* W = (gate == 0) ? Wf : (gate == 1) ? Wi : (gate == 2) ? Wg_ : Wo;
        float wx = W[j * 1024 + k];
        __nv_bfloat16 hi = __float2bfloat16(wx);
        g_Whi[idx] = hi;
        g_Wlo[idx] = __float2bfloat16(wx - __bfloat162float(hi));
        float wh = W[j * 1024 + 512 + k];
        __nv_bfloat16 rh = __float2bfloat16(wh);
        g_Rhi[idx] = rh;
        g_Rlo[idx] = __float2bfloat16(wh - __bfloat162float(rh));
        if (k == 0) {
            const float* bb = (gate == 0) ? bf : (gate == 1) ? bi : (gate == 2) ? bg : bo;
            g_bias[r] = bb[j];
        }
    }
    if (idx < BB * HD) {
        g_hbhi[0][idx] = __float2bfloat16(0.f);
        g_hblo[0][idx] = __float2bfloat16(0.f);
    }
}

// ---------------- split X into bf16 hi/lo ----------------
__global__ void split_x(const float* __restrict__ X) {
    size_t i = (size_t)blockIdx.x * blockDim.x + threadIdx.x;  // float4 index
    if (i < (size_t)MTOT * DIN / 4) {
        float4 v = __ldg((const float4*)X + i);
        __nv_bfloat16 h0 = __float2bfloat16(v.x), h1 = __float2bfloat16(v.y);
        __nv_bfloat16 h2 = __float2bfloat16(v.z), h3 = __float2bfloat16(v.w);
        __nv_bfloat162* ph = (__nv_bfloat162*)g_Xhi;
        __nv_bfloat162* pl = (__nv_bfloat162*)g_Xlo;
        ph[i * 2] = __nv_bfloat162(h0, h1);
        ph[i * 2 + 1] = __nv_bfloat162(h2, h3);
        pl[i * 2] = __nv_bfloat162(__float2bfloat16(v.x - __bfloat162float(h0)),
                                   __float2bfloat16(v.y - __bfloat162float(h1)));
        pl[i * 2 + 1] = __nv_bfloat162(__float2bfloat16(v.z - __bfloat162float(h2)),
                                       __float2bfloat16(v.w - __bfloat162float(h3)));
    }
}

// ---------------- xproj via mma.sync (proven in R8) ----------------
__global__ void __launch_bounds__(256) xproj_mma(int dummy) {
    extern __shared__ char smraw[];
    char* smp = (char*)(((uintptr_t)smraw + 127) & ~(uintptr_t)127);
    uint32_t ub = smem_u32(smp);
    int tid = threadIdx.x, wid = tid >> 5, lane = tid & 31;
    int wr = wid & 1, wm = wid >> 1;
    int r0 = blockIdx.y * 128, m0 = blockIdx.x * 128;

    float acc[4][4][4];
#pragma unroll
    for (int f = 0; f < 4; f++)
#pragma unroll
        for (int mf = 0; mf < 4; mf++)
#pragma unroll
            for (int q = 0; q < 4; q++) acc[f][mf][q] = 0.f;

    const __nv_bfloat16* srcs[4] = {
        g_Whi + (size_t)r0 * DIN, g_Wlo + (size_t)r0 * DIN,
        g_Xhi + (size_t)m0 * DIN, g_Xlo + (size_t)m0 * DIN };

    for (int kc = 0; kc < 8; kc++) {
        __syncthreads();
#pragma unroll
        for (int mat = 0; mat < 4; mat++) {
            const float4* src = (const float4*)srcs[mat];
            char* dst = smp + mat * 16384;
#pragma unroll
            for (int it = 0; it < 4; it++) {
                int idx = tid + it * 256;
                int row = idx & 127;
                int kt8 = idx >> 7;
                uint32_t off = (uint32_t)(((row >> 3) * 8 + kt8) * 128 + (row & 7) * 16);
                *(float4*)(dst + off) = __ldg(src + (size_t)row * 64 + kc * 8 + kt8);
            }
        }
        __syncthreads();
        uint32_t aH = ub, aL = ub + 16384, bH = ub + 32768, bL = ub + 49152;
#pragma unroll
        for (int kk = 0; kk < 4; kk++) {
            uint32_t aoff[4], boff[2];
#pragma unroll
            for (int f = 0; f < 4; f++)
                aoff[f] = (uint32_t)(((wr * 8 + f * 2 + ((lane >> 3) & 1)) * 8
                                      + (2 * kk + (lane >> 4))) * 128 + (lane & 7) * 16);
#pragma unroll
            for (int p = 0; p < 2; p++)
                boff[p] = (uint32_t)(((wm * 4 + 2 * p + (lane >> 4)) * 8
                                      + (2 * kk + ((lane >> 3) & 1))) * 128 + (lane & 7) * 16);

            uint32_t ah[4][4], bh[4][2];
#pragma unroll
            for (int f = 0; f < 4; f++)
                ldsm4(ah[f][0], ah[f][1], ah[f][2], ah[f][3], aH + aoff[f]);
#pragma unroll
            for (int p = 0; p < 2; p++)
                ldsm4(bh[2 * p][0], bh[2 * p][1], bh[2 * p + 1][0], bh[2 * p + 1][1],
                      bH + boff[p]);
#pragma unroll
            for (int f = 0; f < 4; f++)
#pragma unroll
                for (int mf = 0; mf < 4; mf++)
                    mma16816(acc[f][mf], ah[f], bh[mf]);
            {
                uint32_t bl[4][2];
#pragma unroll
                for (int p = 0; p < 2; p++)
                    ldsm4(bl[2 * p][0], bl[2 * p][1], bl[2 * p + 1][0], bl[2 * p + 1][1],
                          bL + boff[p]);
#pragma unroll
                for (int f = 0; f < 4; f++)
#pragma unroll
                    for (int mf = 0; mf < 4; mf++)
                        mma16816(acc[f][mf], ah[f], bl[mf]);
            }
            {
#pragma unroll
                for (int f = 0; f < 4; f++) {
                    uint32_t av[4];
                    ldsm4(av[0], av[1], av[2], av[3], aL + aoff[f]);
#pragma unroll
                    for (int mf = 0; mf < 4; mf++)
                        mma16816(acc[f][mf], av, bh[mf]);
                }
            }
        }
    }
    int g = lane >> 2, t2 = (lane & 3) * 2;
#pragma unroll
    for (int f = 0; f < 4; f++) {
        int r = r0 + wr * 64 + f * 16 + g;
        float b0 = __ldg(&g_bias[r]);
        float b1 = __ldg(&g_bias[r + 8]);
#pragma unroll
        for (int mf = 0; mf < 4; mf++) {
            int m = m0 + wm * 32 + mf * 8 + t2;
            float2 v0 = make_float2(acc[f][mf][0] + b0, acc[f][mf][1] + b0);
            float2 v1 = make_float2(acc[f][mf][2] + b1, acc[f][mf][3] + b1);
            *(float2*)&g_xproj[(size_t)r * MTOT + m] = v0;
            *(float2*)&g_xproj[(size_t)(r + 8) * MTOT + m] = v1;
        }
    }
}

// ---------------- persistent tensor-core LSTM recurrence ----------------
__device__ __forceinline__ float sigf(float x) { return 1.f / (1.f + expf(-x)); }

__device__ __forceinline__ void grid_sync(int nblocks) {
    __threadfence();
    __syncthreads();
    if (threadIdx.x == 0) {
        unsigned old = *(volatile unsigned*)&g_gen;
        int my = atomicAdd(&g_bar, 1);
        if (my == nblocks - 1) {
            g_bar = 0;
            __threadfence();
            atomicAdd(&g_gen, 1);
        } else {
            while (*(volatile unsigned*)&g_gen == old) {}
        }
        __threadfence();
    }
    __syncthreads();
}

// smem byte offsets (dynamic)
#define SW_HI   0          // W hi tiled: 16r x 512k, (rt*64+kt)*128 + inrow*16    (16KB)
#define SW_LO   16384
#define SB_BASE 32768      // h chunks: 2 bufs x (hi 16KB + lo 16KB)               (64KB)
#define SP_OFF  98304      // float[16][132] preacts                                (8448B)
#define SH_HI   106752     // bf16[4][128] h-out staging hi                         (1KB)
#define SH_LO   107776
#define SM_TOT  108800

// load one 64k x 128b chunk of h (hi+lo) into smem tile buffer via cp.async.cg
__device__ __forceinline__ void issue_chunk(uint32_t sbuf, const __nv_bfloat16* hbi,
                                            const __nv_bfloat16* hbl, int kc, int tid) {
#pragma unroll
    for (int q = 0; q < 4; q++) {
        int idx = q * 256 + tid;               // 0..1023
        int b = idx >> 3, seg = idx & 7;
        uint32_t soff = (uint32_t)((((b >> 3) * 8 + seg) * 128 + (b & 7) * 16));
        size_t goff = (size_t)b * 512 + kc * 64 + seg * 8;
        cpasync16(sbuf + soff, hbi + goff);
        cpasync16(sbuf + 16384 + soff, hbl + goff);
    }
}

// 128 CTAs x 256 threads. CTA owns 4 hidden units j0..j0+3 x 4 gates = 16 rows.
// Local row = gate*4+u. Warp w covers batch cols [w*16, w*16+16).
__global__ void __launch_bounds__(256, 1) lstm_tc(float* __restrict__ out) {
    extern __shared__ char sm[];
    uint32_t ub = smem_u32(sm);
    float* sP = (float*)(sm + SP_OFF);
    __nv_bfloat16* sHhi = (__nv_bfloat16*)(sm + SH_HI);
    __nv_bfloat16* sHlo = (__nv_bfloat16*)(sm + SH_LO);
    int tid = threadIdx.x, wid = tid >> 5, lane = tid & 31;
    int j0 = blockIdx.x * 4;

    // tile W hi/lo into smem once (resident all 512 steps)
#pragma unroll
    for (int q = 0; q < 4; q++) {
        int idx = q * 256 + tid;               // 0..1023
        int rl = idx >> 6, k16 = idx & 63;
        int rg = (rl >> 2) * 512 + j0 + (rl & 3);
        uint32_t soff = (uint32_t)((((rl >> 3) * 64 + k16) * 128 + (rl & 7) * 16));
        *(float4*)(sm + SW_HI + soff) = *(const float4*)&g_Rhi[(size_t)rg * 512 + k16 * 8];
        *(float4*)(sm + SW_LO + soff) = *(const float4*)&g_Rlo[(size_t)rg * 512 + k16 * 8];
    }

    float c0 = 0.f, c1 = 0.f;
    int eb = tid >> 1;             // epilogue batch
    int eu = (tid & 1) * 2;        // epilogue u base
    __syncthreads();

    for (int t = 0; t < TT; t++) {
        int p = t & 1;
        const __nv_bfloat16* hbi = g_hbhi[p];
        const __nv_bfloat16* hbl = g_hblo[p];

        // preload xproj into sP (pre-activations start = xproj, bias folded)
#pragma unroll
        for (int q = 0; q < 2; q++) {
            int f4 = q * 256 + tid;            // 0..511
            int row = f4 >> 5, cc4 = (f4 & 31) * 4;
            int rg = (row >> 2) * 512 + j0 + (row & 3);
            *(float4*)&sP[row * 132 + cc4] =
                __ldg((const float4*)&g_xproj[(size_t)rg * MTOT + (size_t)t * 128 + cc4]);
        }

        // prologue: issue chunks 0,1
        issue_chunk(ub + SB_BASE, hbi, hbl, 0, tid);
        CP_COMMIT();
        issue_chunk(ub + SB_BASE + 32768, hbi, hbl, 1, tid);
        CP_COMMIT();

        float acc[2][2][4];                    // [chunk parity][n8 tile][4]
#pragma unroll
        for (int a = 0; a < 2; a++)
#pragma unroll
            for (int n = 0; n < 2; n++)
#pragma unroll
                for (int q = 0; q < 4; q++) acc[a][n][q] = 0.f;

        for (int kc = 0; kc < 8; kc++) {
            if (kc < 7) { CP_WAIT1(); } else { CP_WAIT0(); }
            __syncthreads();
            uint32_t bb = ub + SB_BASE + (kc & 1) * 32768;
            int kp = kc & 1;
#pragma unroll
            for (int kt = 0; kt < 4; kt++) {
                int ktA = kc * 8 + 2 * kt;
                uint32_t aoff = (uint32_t)(((((lane >> 3) & 1) * 64 + ktA + (lane >> 4)) * 128
                                            + (lane & 7) * 16));
                uint32_t boff = (uint32_t)((((2 * wid + (lane >> 4)) * 8 + 2 * kt
                                             + ((lane >> 3) & 1)) * 128 + (lane & 7) * 16));
                uint32_t ah[4], al[4], bh[4], bl[4];
                ldsm4(ah[0], ah[1], ah[2], ah[3], ub + SW_HI + aoff);
                ldsm4(bh[0], bh[1], bh[2], bh[3], bb + boff);
                ldsm4(al[0], al[1], al[2], al[3], ub + SW_LO + aoff);
                ldsm4(bl[0], bl[1], bl[2], bl[3], bb + 16384 + boff);
                mma16816(acc[kp][0], ah, bh + 0);
                mma16816(acc[kp][1], ah, bh + 2);
                mma16816(acc[kp][0], ah, bl + 0);
                mma16816(acc[kp][1], ah, bl + 2);
                mma16816(acc[kp][0], al, bh + 0);
                mma16816(acc[kp][1], al, bh + 2);
            }
            __syncthreads();
            if (kc + 2 < 8) {
                issue_chunk(ub + SB_BASE + (kc & 1) * 32768, hbi, hbl, kc + 2, tid);
                CP_COMMIT();
            }
        }

        // add accumulators into sP (each (r,b) has a unique owner thread)
        {
            int g = lane >> 2, cB = wid * 16 + (lane & 3) * 2;
#pragma unroll
            for (int n = 0; n < 2; n++) {
                int col = cB + n * 8;
                sP[g * 132 + col]       += acc[0][n][0] + acc[1][n][0];
                sP[g * 132 + col + 1]   += acc[0][n][1] + acc[1][n][1];
                sP[(g + 8) * 132 + col]     += acc[0][n][2] + acc[1][n][2];
                sP[(g + 8) * 132 + col + 1] += acc[0][n][3] + acc[1][n][3];
            }
        }
        __syncthreads();

        // cell update: thread owns (b=eb, u=eu..eu+1)
        float hv0, hv1;
        {
            float pf = sP[(0 + eu) * 132 + eb];
            float pi = sP[(4 + eu) * 132 + eb];
            float pg = sP[(8 + eu) * 132 + eb];
            float po = sP[(12 + eu) * 132 + eb];
            float fg = sigf(pf), ig = sigf(pi), gg = tanhf(pg), og = sigf(po);
            c0 = fg * c0 + ig * gg;
            hv0 = og * tanhf(c0);
        }
        {
            int u = eu + 1;
            float pf = sP[(0 + u) * 132 + eb];
            float pi = sP[(4 + u) * 132 + eb];
            float pg = sP[(8 + u) * 132 + eb];
            float po = sP[(12 + u) * 132 + eb];
            float fg = sigf(pf), ig = sigf(pi), gg = tanhf(pg), og = sigf(po);
            c1 = fg * c1 + ig * gg;
            hv1 = og * tanhf(c1);
        }
        {
            __nv_bfloat16 h0 = __float2bfloat16(hv0);
            sHhi[eu * 128 + eb] = h0;
            sHlo[eu * 128 + eb] = __float2bfloat16(hv0 - __bfloat162float(h0));
            __nv_bfloat16 h1 = __float2bfloat16(hv1);
            sHhi[(eu + 1) * 128 + eb] = h1;
            sHlo[(eu + 1) * 128 + eb] = __float2bfloat16(hv1 - __bfloat162float(h1));
        }
        *(float2*)&out[((size_t)t * 128 + eb) * 512 + j0 + eu] = make_float2(hv0, hv1);
        if (t == TT - 1) {
            *(float2*)&out[OUTBASE + (size_t)eb * 512 + j0 + eu] = make_float2(hv0, hv1);
            *(float2*)&out[OUTBASE + (size_t)BB * HD + (size_t)eb * 512 + j0 + eu] =
                make_float2(c0, c1);
        }
        __syncthreads();

        // cooperative h write: [b][k] layout, 4 bf16 (8B) per b per matrix
        {
            int mat = tid >> 7, b = tid & 127;
            const __nv_bfloat16* s = mat ? sHlo : sHhi;
            unsigned short v0 = *(const unsigned short*)&s[0 * 128 + b];
            unsigned short v1 = *(const unsigned short*)&s[1 * 128 + b];
            unsigned short v2 = *(const unsigned short*)&s[2 * 128 + b];
            unsigned short v3 = *(const unsigned short*)&s[3 * 128 + b];
            ushort4 pack = make_ushort4(v0, v1, v2, v3);
            __nv_bfloat16* dst = (mat ? g_hblo : g_hbhi)[p ^ 1] + (size_t)b * 512 + j0;
            *(ushort4*)dst = pack;
        }
        grid_sync(128);
    }
}

extern "C" void kernel_launch(void* const* d_in, const int* in_sizes, int n_in,
                              void* d_out, int out_size) {
    const float* X  = (const float*)d_in[0];
    const float* Wf = (const float*)d_in[1];
    const float* bf = (const float*)d_in[2];
    const float* Wi = (const float*)d_in[3];
    const float* bi = (const float*)d_in[4];
    const float* Wg = (const float*)d_in[5];
    const float* bg = (const float*)d_in[6];
    const float* Wo = (const float*)d_in[7];
    const float* bo = (const float*)d_in[8];
    float* out = (float*)d_out;

    const int mma_smem = 4 * 16384 + 128;   // ~64.1KB
    cudaFuncSetAttribute(xproj_mma, cudaFuncAttributeMaxDynamicSharedMemorySize, mma_smem);
    cudaFuncSetAttribute(lstm_tc, cudaFuncAttributeMaxDynamicSharedMemorySize, SM_TOT);

    pack_kernel<<<(NR * DIN + 255) / 256, 256>>>(Wf, Wi, Wg, Wo, bf, bi, bg, bo);
    split_x<<<(int)(((size_t)MTOT * DIN / 4 + 255) / 256), 256>>>(X);
    dim3 ggrid(MTOT / 128, NR / 128);   // (512, 16)
    xproj_mma<<<ggrid, 256, mma_smem>>>(0);
    lstm_tc<<<128, 256, SM_TOT>>>(out);
}

// round 10
// speedup vs baseline: 1.6219x; 1.0841x over previous
#include <cuda_runtime.h>
#include <cuda_bf16.h>
#include <math.h>
#include <stdint.h>

#define TT 512
#define BB 128
#define DIN 512
#define HD 512
#define NR 2048
#define MTOT (TT * BB)          // 65536
#define OUTBASE ((size_t)TT * BB * HD)

// ---------------- scratch ----------------
__device__ __nv_bfloat16 g_Xhi[(size_t)MTOT * DIN];
__device__ __nv_bfloat16 g_Xlo[(size_t)MTOT * DIN];
__device__ __nv_bfloat16 g_Whi[NR * DIN];        // x-part weights hi
__device__ __nv_bfloat16 g_Wlo[NR * DIN];        // x-part weights lo
__device__ __nv_bfloat16 g_Rhi[NR * HD];         // h-part weights hi
__device__ __nv_bfloat16 g_Rlo[NR * HD];         // h-part weights lo
__device__ float g_bias[NR];
__device__ float g_xproj[(size_t)NR * MTOT];     // [r][m]
__device__ __nv_bfloat16 g_hbhi[2][BB * HD];     // h hi, [b][k], double buffered
__device__ __nv_bfloat16 g_hblo[2][BB * HD];     // h lo
__device__ volatile unsigned g_flags[128];        // barrier arrive flags
__device__ volatile unsigned g_release;           // barrier release word

// ---------------- PTX helpers (sm_80-compatible ISA only) ----------------
__device__ __forceinline__ uint32_t smem_u32(const void* p) {
    uint32_t a;
    asm("{ .reg .u64 t; cvta.to.shared.u64 t, %1; cvt.u32.u64 %0, t; }" : "=r"(a) : "l"(p));
    return a;
}

__device__ __forceinline__ void ldsm4(uint32_t& r0, uint32_t& r1, uint32_t& r2, uint32_t& r3,
                                      uint32_t addr) {
    asm volatile("ldmatrix.sync.aligned.m8n8.x4.shared.b16 {%0,%1,%2,%3}, [%4];"
                 : "=r"(r0), "=r"(r1), "=r"(r2), "=r"(r3) : "r"(addr));
}

__device__ __forceinline__ void mma16816(float* c, const uint32_t* a, const uint32_t* b) {
    asm volatile("mma.sync.aligned.m16n8k16.row.col.f32.bf16.bf16.f32 "
                 "{%0,%1,%2,%3}, {%4,%5,%6,%7}, {%8,%9}, {%0,%1,%2,%3};"
                 : "+f"(c[0]), "+f"(c[1]), "+f"(c[2]), "+f"(c[3])
                 : "r"(a[0]), "r"(a[1]), "r"(a[2]), "r"(a[3]), "r"(b[0]), "r"(b[1]));
}

__device__ __forceinline__ void cpasync16(uint32_t saddr, const void* g) {
    asm volatile("cp.async.cg.shared.global [%0], [%1], 16;" :: "r"(saddr), "l"(g));
}
#define CP_COMMIT() asm volatile("cp.async.commit_group;" ::: "memory")
#define CP_WAIT1()  asm volatile("cp.async.wait_group 1;" ::: "memory")
#define CP_WAIT0()  asm volatile("cp.async.wait_group 0;" ::: "memory")

// ---------------- pack weights (bf16 hi/lo both halves), zero h0 ----------------
__global__ void pack_kernel(const float* __restrict__ Wf, const float* __restrict__ Wi,
                            const float* __restrict__ Wg_, const float* __restrict__ Wo,
                            const float* __restrict__ bf, const float* __restrict__ bi,
                            const float* __restrict__ bg, const float* __restrict__ bo) {
    int idx = blockIdx.x * blockDim.x + threadIdx.x;
    if (idx < NR * DIN) {
        int r = idx >> 9;
        int k = idx & 511;
        int gate = r >> 9;
        int j = r & 511;
        const float* W = (gate == 0) ? Wf : (gate == 1) ? Wi : (gate == 2) ? Wg_ : Wo;
        float wx = W[j * 1024 + k];
        __nv_bfloat16 hi = __float2bfloat16(wx);
        g_Whi[idx] = hi;
        g_Wlo[idx] = __float2bfloat16(wx - __bfloat162float(hi));
        float wh = W[j * 1024 + 512 + k];
        __nv_bfloat16 rh = __float2bfloat16(wh);
        g_Rhi[idx] = rh;
        g_Rlo[idx] = __float2bfloat16(wh - __bfloat162float(rh));
        if (k == 0) {
            const float* bb = (gate == 0) ? bf : (gate == 1) ? bi : (gate == 2) ? bg : bo;
            g_bias[r] = bb[j];
        }
    }
    if (idx < BB * HD) {
        g_hbhi[0][idx] = __float2bfloat16(0.f);
        g_hblo[0][idx] = __float2bfloat16(0.f);
    }
}

// ---------------- split X into bf16 hi/lo ----------------
__global__ void split_x(const float* __restrict__ X) {
    size_t i = (size_t)blockIdx.x * blockDim.x + threadIdx.x;  // float4 index
    if (i < (size_t)MTOT * DIN / 4) {
        float4 v = __ldg((const float4*)X + i);
        __nv_bfloat16 h0 = __float2bfloat16(v.x), h1 = __float2bfloat16(v.y);
        __nv_bfloat16 h2 = __float2bfloat16(v.z), h3 = __float2bfloat16(v.w);
        __nv_bfloat162* ph = (__nv_bfloat162*)g_Xhi;
        __nv_bfloat162* pl = (__nv_bfloat162*)g_Xlo;
        ph[i * 2] = __nv_bfloat162(h0, h1);
        ph[i * 2 + 1] = __nv_bfloat162(h2, h3);
        pl[i * 2] = __nv_bfloat162(__float2bfloat16(v.x - __bfloat162float(h0)),
                                   __float2bfloat16(v.y - __bfloat162float(h1)));
        pl[i * 2 + 1] = __nv_bfloat162(__float2bfloat16(v.z - __bfloat162float(h2)),
                                       __float2bfloat16(v.w - __bfloat162float(h3)));
    }
}

// ---------------- xproj via mma.sync (proven in R8) ----------------
__global__ void __launch_bounds__(256) xproj_mma(int dummy) {
    extern __shared__ char smraw[];
    char* smp = (char*)(((uintptr_t)smraw + 127) & ~(uintptr_t)127);
    uint32_t ub = smem_u32(smp);
    int tid = threadIdx.x, wid = tid >> 5, lane = tid & 31;
    int wr = wid & 1, wm = wid >> 1;
    int r0 = blockIdx.y * 128, m0 = blockIdx.x * 128;

    float acc[4][4][4];
#pragma unroll
    for (int f = 0; f < 4; f++)
#pragma unroll
        for (int mf = 0; mf < 4; mf++)
#pragma unroll
            for (int q = 0; q < 4; q++) acc[f][mf][q] = 0.f;

    const __nv_bfloat16* srcs[4] = {
        g_Whi + (size_t)r0 * DIN, g_Wlo + (size_t)r0 * DIN,
        g_Xhi + (size_t)m0 * DIN, g_Xlo + (size_t)m0 * DIN };

    for (int kc = 0; kc < 8; kc++) {
        __syncthreads();
#pragma unroll
        for (int mat = 0; mat < 4; mat++) {
            const float4* src = (const float4*)srcs[mat];
            char* dst = smp + mat * 16384;
#pragma unroll
            for (int it = 0; it < 4; it++) {
                int idx = tid + it * 256;
                int row = idx & 127;
                int kt8 = idx >> 7;
                uint32_t off = (uint32_t)(((row >> 3) * 8 + kt8) * 128 + (row & 7) * 16);
                *(float4*)(dst + off) = __ldg(src + (size_t)row * 64 + kc * 8 + kt8);
            }
        }
        __syncthreads();
        uint32_t aH = ub, aL = ub + 16384, bH = ub + 32768, bL = ub + 49152;
#pragma unroll
        for (int kk = 0; kk < 4; kk++) {
            uint32_t aoff[4], boff[2];
#pragma unroll
            for (int f = 0; f < 4; f++)
                aoff[f] = (uint32_t)(((wr * 8 + f * 2 + ((lane >> 3) & 1)) * 8
                                      + (2 * kk + (lane >> 4))) * 128 + (lane & 7) * 16);
#pragma unroll
            for (int p = 0; p < 2; p++)
                boff[p] = (uint32_t)(((wm * 4 + 2 * p + (lane >> 4)) * 8
                                      + (2 * kk + ((lane >> 3) & 1))) * 128 + (lane & 7) * 16);

            uint32_t ah[4][4], bh[4][2];
#pragma unroll
            for (int f = 0; f < 4; f++)
                ldsm4(ah[f][0], ah[f][1], ah[f][2], ah[f][3], aH + aoff[f]);
#pragma unroll
            for (int p = 0; p < 2; p++)
                ldsm4(bh[2 * p][0], bh[2 * p][1], bh[2 * p + 1][0], bh[2 * p + 1][1],
                      bH + boff[p]);
#pragma unroll
            for (int f = 0; f < 4; f++)
#pragma unroll
                for (int mf = 0; mf < 4; mf++)
                    mma16816(acc[f][mf], ah[f], bh[mf]);
            {
                uint32_t bl[4][2];
#pragma unroll
                for (int p = 0; p < 2; p++)
                    ldsm4(bl[2 * p][0], bl[2 * p][1], bl[2 * p + 1][0], bl[2 * p + 1][1],
                          bL + boff[p]);
#pragma unroll
                for (int f = 0; f < 4; f++)
#pragma unroll
                    for (int mf = 0; mf < 4; mf++)
                        mma16816(acc[f][mf], ah[f], bl[mf]);
            }
            {
#pragma unroll
                for (int f = 0; f < 4; f++) {
                    uint32_t av[4];
                    ldsm4(av[0], av[1], av[2], av[3], aL + aoff[f]);
#pragma unroll
                    for (int mf = 0; mf < 4; mf++)
                        mma16816(acc[f][mf], av, bh[mf]);
                }
            }
        }
    }
    int g = lane >> 2, t2 = (lane & 3) * 2;
#pragma unroll
    for (int f = 0; f < 4; f++) {
        int r = r0 + wr * 64 + f * 16 + g;
        float b0 = __ldg(&g_bias[r]);
        float b1 = __ldg(&g_bias[r + 8]);
#pragma unroll
        for (int mf = 0; mf < 4; mf++) {
            int m = m0 + wm * 32 + mf * 8 + t2;
            float2 v0 = make_float2(acc[f][mf][0] + b0, acc[f][mf][1] + b0);
            float2 v1 = make_float2(acc[f][mf][2] + b1, acc[f][mf][3] + b1);
            *(float2*)&g_xproj[(size_t)r * MTOT + m] = v0;
            *(float2*)&g_xproj[(size_t)(r + 8) * MTOT + m] = v1;
        }
    }
}

// ---------------- persistent tensor-core LSTM recurrence ----------------
__device__ __forceinline__ float sigf(float x) { return 1.f / (1.f + expf(-x)); }

// smem byte offsets (dynamic)
#define SW_HI   0          // W hi tiled: 16r x 512k                               (16KB)
#define SW_LO   16384
#define SB_BASE 32768      // h chunks: 3 bufs x (hi 16KB + lo 16KB)               (96KB)
#define SP_OFF  131072     // float[16][132] preacts                                (8448B)
#define SH_HI   139520     // bf16[4][128] h-out staging hi                         (1KB)
#define SH_LO   140544
#define SM_TOT  141568

// load one 64k x 128b chunk of h (hi+lo) into smem tile buffer via cp.async.cg
__device__ __forceinline__ void issue_chunk(uint32_t sbuf, const __nv_bfloat16* hbi,
                                            const __nv_bfloat16* hbl, int kc, int tid) {
#pragma unroll
    for (int q = 0; q < 4; q++) {
        int idx = q * 256 + tid;               // 0..1023
        int b = idx >> 3, seg = idx & 7;
        uint32_t soff = (uint32_t)((((b >> 3) * 8 + seg) * 128 + (b & 7) * 16));
        size_t goff = (size_t)b * 512 + kc * 64 + seg * 8;
        cpasync16(sbuf + soff, hbi + goff);
        cpasync16(sbuf + 16384 + soff, hbl + goff);
    }
}

// 128 CTAs x 256 threads. CTA owns 4 hidden units j0..j0+3 x 4 gates = 16 rows.
__global__ void __launch_bounds__(256, 1) lstm_tc(float* __restrict__ out) {
    extern __shared__ char sm[];
    uint32_t ub = smem_u32(sm);
    float* sP = (float*)(sm + SP_OFF);
    __nv_bfloat16* sHhi = (__nv_bfloat16*)(sm + SH_HI);
    __nv_bfloat16* sHlo = (__nv_bfloat16*)(sm + SH_LO);
    int tid = threadIdx.x, wid = tid >> 5, lane = tid & 31;
    int j0 = blockIdx.x * 4;

    // replay-safe barrier base: monotonic generation carried across launches
    unsigned gbase = g_release;

    // tile W hi/lo into smem once (resident all 512 steps)
#pragma unroll
    for (int q = 0; q < 4; q++) {
        int idx = q * 256 + tid;               // 0..1023
        int rl = idx >> 6, k16 = idx & 63;
        int rg = (rl >> 2) * 512 + j0 + (rl & 3);
        uint32_t soff = (uint32_t)((((rl >> 3) * 64 + k16) * 128 + (rl & 7) * 16));
        *(float4*)(sm + SW_HI + soff) = *(const float4*)&g_Rhi[(size_t)rg * 512 + k16 * 8];
        *(float4*)(sm + SW_LO + soff) = *(const float4*)&g_Rlo[(size_t)rg * 512 + k16 * 8];
    }

    float c0 = 0.f, c1 = 0.f;
    int eb = tid >> 1;             // epilogue batch
    int eu = (tid & 1) * 2;        // epilogue u base
    __syncthreads();

    for (int t = 0; t < TT; t++) {
        int p = t & 1;
        const __nv_bfloat16* hbi = g_hbhi[p];
        const __nv_bfloat16* hbl = g_hblo[p];

        // prologue: issue chunks 0,1
        issue_chunk(ub + SB_BASE, hbi, hbl, 0, tid);
        CP_COMMIT();
        issue_chunk(ub + SB_BASE + 32768, hbi, hbl, 1, tid);
        CP_COMMIT();

        // xproj preload (L2 path, immune to L1 flush), latency hides under pipeline
        float4 xv[2];
#pragma unroll
        for (int q = 0; q < 2; q++) {
            int f4 = q * 256 + tid;            // 0..511
            int row = f4 >> 5, cc4 = (f4 & 31) * 4;
            int rg = (row >> 2) * 512 + j0 + (row & 3);
            xv[q] = __ldcg((const float4*)&g_xproj[(size_t)rg * MTOT + (size_t)t * 128 + cc4]);
        }
#pragma unroll
        for (int q = 0; q < 2; q++) {
            int f4 = q * 256 + tid;
            int row = f4 >> 5, cc4 = (f4 & 31) * 4;
            *(float4*)&sP[row * 132 + cc4] = xv[q];
        }

        float acc[3][2][4];                    // [product hh/hl/lh][n8 tile][4]
#pragma unroll
        for (int a = 0; a < 3; a++)
#pragma unroll
            for (int n = 0; n < 2; n++)
#pragma unroll
                for (int q = 0; q < 4; q++) acc[a][n][q] = 0.f;

        for (int kc = 0; kc < 8; kc++) {
            if (kc < 7) { CP_WAIT1(); } else { CP_WAIT0(); }
            __syncthreads();
            // issue-ahead: chunk kc+2 into the buffer retired at iteration kc-1
            if (kc + 2 < 8) {
                issue_chunk(ub + SB_BASE + ((kc + 2) % 3) * 32768, hbi, hbl, kc + 2, tid);
                CP_COMMIT();
            }
            uint32_t bb = ub + SB_BASE + (kc % 3) * 32768;
#pragma unroll
            for (int kt = 0; kt < 4; kt++) {
                int ktA = kc * 8 + 2 * kt;
                uint32_t aoff = (uint32_t)(((((lane >> 3) & 1) * 64 + ktA + (lane >> 4)) * 128
                                            + (lane & 7) * 16));
                uint32_t boff = (uint32_t)((((2 * wid + (lane >> 4)) * 8 + 2 * kt
                                             + ((lane >> 3) & 1)) * 128 + (lane & 7) * 16));
                uint32_t ah[4], al[4], bh[4], bl[4];
                ldsm4(ah[0], ah[1], ah[2], ah[3], ub + SW_HI + aoff);
                ldsm4(bh[0], bh[1], bh[2], bh[3], bb + boff);
                ldsm4(al[0], al[1], al[2], al[3], ub + SW_LO + aoff);
                ldsm4(bl[0], bl[1], bl[2], bl[3], bb + 16384 + boff);
                // 6 independent accumulator chains
                mma16816(acc[0][0], ah, bh + 0);
                mma16816(acc[0][1], ah, bh + 2);
                mma16816(acc[1][0], ah, bl + 0);
                mma16816(acc[1][1], ah, bl + 2);
                mma16816(acc[2][0], al, bh + 0);
                mma16816(acc[2][1], al, bh + 2);
            }
        }
        __syncthreads();

        // add accumulators into sP (each (r,b) has a unique owner thread)
        {
            int g = lane >> 2, cB = wid * 16 + (lane & 3) * 2;
#pragma unroll
            for (int n = 0; n < 2; n++) {
                int col = cB + n * 8;
                sP[g * 132 + col]       += acc[0][n][0] + acc[1][n][0] + acc[2][n][0];
                sP[g * 132 + col + 1]   += acc[0][n][1] + acc[1][n][1] + acc[2][n][1];
                sP[(g + 8) * 132 + col]     += acc[0][n][2] + acc[1][n][2] + acc[2][n][2];
                sP[(g + 8) * 132 + col + 1] += acc[0][n][3] + acc[1][n][3] + acc[2][n][3];
            }
        }
        __syncthreads();

        // cell update: thread owns (b=eb, u=eu..eu+1)
        float hv0, hv1;
        {
            float pf = sP[(0 + eu) * 132 + eb];
            float pi = sP[(4 + eu) * 132 + eb];
            float pg = sP[(8 + eu) * 132 + eb];
            float po = sP[(12 + eu) * 132 + eb];
            float fg = sigf(pf), ig = sigf(pi), gg = tanhf(pg), og = sigf(po);
            c0 = fg * c0 + ig * gg;
            hv0 = og * tanhf(c0);
        }
        {
            int u = eu + 1;
            float pf = sP[(0 + u) * 132 + eb];
            float pi = sP[(4 + u) * 132 + eb];
            float pg = sP[(8 + u) * 132 + eb];
            float po = sP[(12 + u) * 132 + eb];
            float fg = sigf(pf), ig = sigf(pi), gg = tanhf(pg), og = sigf(po);
            c1 = fg * c1 + ig * gg;
            hv1 = og * tanhf(c1);
        }
        {
            __nv_bfloat16 h0 = __float2bfloat16(hv0);
            sHhi[eu * 128 + eb] = h0;
            sHlo[eu * 128 + eb] = __float2bfloat16(hv0 - __bfloat162float(h0));
            __nv_bfloat16 h1 = __float2bfloat16(hv1);
            sHhi[(eu + 1) * 128 + eb] = h1;
            sHlo[(eu + 1) * 128 + eb] = __float2bfloat16(hv1 - __bfloat162float(h1));
        }
        *(float2*)&out[((size_t)t * 128 + eb) * 512 + j0 + eu] = make_float2(hv0, hv1);
        if (t == TT - 1) {
            *(float2*)&out[OUTBASE + (size_t)eb * 512 + j0 + eu] = make_float2(hv0, hv1);
            *(float2*)&out[OUTBASE + (size_t)BB * HD + (size_t)eb * 512 + j0 + eu] =
                make_float2(c0, c1);
        }
        __syncthreads();

        // cooperative h write: [b][k] layout, 4 bf16 (8B) per b per matrix
        {
            int mat = tid >> 7, b = tid & 127;
            const __nv_bfloat16* s = mat ? sHlo : sHhi;
            unsigned short v0 = *(const unsigned short*)&s[0 * 128 + b];
            unsigned short v1 = *(const unsigned short*)&s[1 * 128 + b];
            unsigned short v2 = *(const unsigned short*)&s[2 * 128 + b];
            unsigned short v3 = *(const unsigned short*)&s[3 * 128 + b];
            ushort4 pack = make_ushort4(v0, v1, v2, v3);
            __nv_bfloat16* dst = (mat ? g_hblo : g_hbhi)[p ^ 1] + (size_t)b * 512 + j0;
            *(ushort4*)dst = pack;
        }

        // distributed-flag grid barrier (skip after final step)
        if (t < TT - 1) {
            unsigned gen = gbase + (unsigned)t + 1u;
            __syncthreads();
            __threadfence();
            if (tid == 0) g_flags[blockIdx.x] = gen;
            if (blockIdx.x == 0) {
                if (tid < 128) {
                    while (g_flags[tid] != gen) {}
                }
                __syncthreads();
                if (tid == 0) g_release = gen;
            }
            if (tid == 0) {
                while (g_release != gen) {}
            }
            __syncthreads();
        }
    }
}

extern "C" void kernel_launch(void* const* d_in, const int* in_sizes, int n_in,
                              void* d_out, int out_size) {
    const float* X  = (const float*)d_in[0];
    const float* Wf = (const float*)d_in[1];
    const float* bf = (const float*)d_in[2];
    const float* Wi = (const float*)d_in[3];
    const float* bi = (const float*)d_in[4];
    const float* Wg = (const float*)d_in[5];
    const float* bg = (const float*)d_in[6];
    const float* Wo = (const float*)d_in[7];
    const float* bo = (const float*)d_in[8];
    float* out = (float*)d_out;

    const int mma_smem = 4 * 16384 + 128;   // ~64.1KB
    cudaFuncSetAttribute(xproj_mma, cudaFuncAttributeMaxDynamicSharedMemorySize, mma_smem);
    cudaFuncSetAttribute(lstm_tc, cudaFuncAttributeMaxDynamicSharedMemorySize, SM_TOT);

    pack_kernel<<<(NR * DIN + 255) / 256, 256>>>(Wf, Wi, Wg, Wo, bf, bi, bg, bo);
    split_x<<<(int)(((size_t)MTOT * DIN / 4 + 255) / 256), 256>>>(X);
    dim3 ggrid(MTOT / 128, NR / 128);   // (512, 16)
    xproj_mma<<<ggrid, 256, mma_smem>>>(0);
    lstm_tc<<<128, 256, SM_TOT>>>(out);
}